// round 17
// baseline (speedup 1.0000x reference)
#include <cuda_runtime.h>
#include <cuda_fp16.h>
#include <cstdint>
#include <math.h>

// tril(A @ B), A,B lower-triangular fp32, N=4096.
// R17 = R15 pipeline (LDG+convert+STS double-buffer) on FULL 128x128 tiles:
//   8 warps of 64x32 (frag-LDS 160B/HMMA vs 192) + B traffic amortized 2x
//   -> L1 68KB/unit ~= tensor 512cyc/unit (balanced; was 92KB -> 736cyc).
//   528 CTAs largest-K-first (80.9 fc/slot avg, corner 128: not makespan-bound).
// Numerics (validated 2.078e-4): x = h + l (fp16 exact residual);
//   D = Ah*Bh + Al*Bh.  A tile: 64B rows, chunk ^= (r>>1)&3 swizzle (R15).
//   B tile: 256B rows, 16B XOR swizzle (R4-proven).

#define NDIM 4096
#define NB   32
#define BK   32
#define THREADS 256

#define ST_AH 0                // A hi: 128 rows * 64B = 8192
#define ST_AL 8192             // A lo: 8192
#define ST_BH 16384            // B hi: 32 k-rows * 256B = 8192
#define STAGE 24576
#define SMEM_DYN (2 * STAGE)   // 49152/CTA; x2 CTAs = 98304

static __device__ __forceinline__ uint32_t smem_u32(const void* p) {
    uint32_t a;
    asm("{ .reg .u64 t; cvta.to.shared.u64 t, %1; cvt.u32.u64 %0, t; }"
        : "=r"(a) : "l"(p));
    return a;
}

static __device__ __forceinline__ uint32_t h2u(__half2 h) {
    return *reinterpret_cast<uint32_t*>(&h);
}

static __device__ __forceinline__ void split2(float x, float y,
                                              uint32_t& h, uint32_t& l) {
    __half2 hh = __floats2half2_rn(x, y);
    float rx = x - __half2float(__low2half(hh));
    float ry = y - __half2float(__high2half(hh));
    l = h2u(__floats2half2_rn(rx, ry));
    h = h2u(hh);
}

static __device__ __forceinline__ void ldm4(uint32_t d[4], uint32_t addr) {
    asm volatile("ldmatrix.sync.aligned.m8n8.x4.shared.b16 {%0,%1,%2,%3}, [%4];"
                 : "=r"(d[0]), "=r"(d[1]), "=r"(d[2]), "=r"(d[3]) : "r"(addr));
}
static __device__ __forceinline__ void ldm4t(uint32_t d[4], uint32_t addr) {
    asm volatile("ldmatrix.sync.aligned.m8n8.x4.trans.shared.b16 {%0,%1,%2,%3}, [%4];"
                 : "=r"(d[0]), "=r"(d[1]), "=r"(d[2]), "=r"(d[3]) : "r"(addr));
}

static __device__ __forceinline__ void mma_f16(float* c, const uint32_t* a,
                                               const uint32_t* b) {
    asm volatile(
        "mma.sync.aligned.m16n8k16.row.col.f32.f16.f16.f32 "
        "{%0,%1,%2,%3}, {%4,%5,%6,%7}, {%8,%9}, {%0,%1,%2,%3};"
        : "+f"(c[0]), "+f"(c[1]), "+f"(c[2]), "+f"(c[3])
        : "r"(a[0]), "r"(a[1]), "r"(a[2]), "r"(a[3]), "r"(b[0]), "r"(b[1]));
}

static __device__ __forceinline__ void sts2(uint32_t addr, uint32_t a, uint32_t b) {
    asm volatile("st.shared.v2.b32 [%0], {%1,%2};" :: "r"(addr), "r"(a), "r"(b)
                 : "memory");
}
static __device__ __forceinline__ void sts4(uint32_t addr, uint32_t a, uint32_t b,
                                            uint32_t c, uint32_t d) {
    asm volatile("st.shared.v4.b32 [%0], {%1,%2,%3,%4};"
                 :: "r"(addr), "r"(a), "r"(b), "r"(c), "r"(d) : "memory");
}

__global__ __launch_bounds__(THREADS, 2)
void trimm_f16(const float* __restrict__ A, const float* __restrict__ B,
               float* __restrict__ C)
{
    extern __shared__ __align__(128) char dyn_smem[];
    const uint32_t sbase = smem_u32(dyn_smem);

    const int tid  = threadIdx.x;
    const int wid  = tid >> 5;
    const int lane = tid & 31;

    // ---- block id -> (bi,bj), largest-K first ----
    int t = blockIdx.x;
    int g = (int)((sqrtf(8.0f * (float)t + 1.0f) - 1.0f) * 0.5f);
    while ((g + 1) * (g + 2) / 2 <= t) ++g;
    while (g * (g + 1) / 2 > t) --g;
    const int bj = t - g * (g + 1) / 2;
    const int bi = bj + (NB - 1) - g;
    const int bm0 = bi * 128, bn0 = bj * 128;
    const int kStart = bn0;
    const int nchunks = ((bm0 + 128) - kStart) >> 5;   // 4..128

    // warp grid 2(m) x 4(n): warp tile 64x32
    const int m0w = (wid & 1) * 64;
    const int n0w = (wid >> 1) * 32;

    // ---- A-tile ldmatrix lane address (64B rows, chunk ^= (r>>1)&3) ----
    const uint32_t swL   = (uint32_t)(((lane & 15) >> 1) & 3);
    const uint32_t laneA = (uint32_t)((lane & 15) * 64) +
                           ((((uint32_t)(lane >> 4)) ^ swL) << 4);
    // B tile: 256B rows (R4-proven swizzle)
    const uint32_t laneBRow = (uint32_t)((lane & 15) * 256);
    const uint32_t laneBCol = (uint32_t)((((lane >> 4) ^ (lane & 7)) << 4));

    // ---- global load + store indices ----
    const int aRow = tid >> 2;             // 0..63 (+64 second pass)
    const int aK8  = (tid & 3) * 8;        // 8 floats/thread
    const int bRow = tid >> 5;             // 0..7 (+8 per pass, 4 passes)
    const int bCol = (tid & 31) * 4;       // 4 floats/thread
    // A store: 16B per plane per pass; chunk = (tid&3), swz key (tid>>3)&3
    const uint32_t aoffBase = (uint32_t)(aRow * 64) +
        ((((uint32_t)(tid & 3)) ^ ((uint32_t)(tid >> 3) & 3u)) << 4);

    float acc[4][4][4];
#pragma unroll
    for (int mt = 0; mt < 4; ++mt)
#pragma unroll
        for (int nt = 0; nt < 4; ++nt)
#pragma unroll
            for (int e = 0; e < 4; ++e) acc[mt][nt][e] = 0.0f;

    float4 ra[4], rb[4];

#define LOAD_CHUNK(k0)                                                          \
    {                                                                           \
        _Pragma("unroll")                                                       \
        for (int p = 0; p < 2; ++p) {                                           \
            const float* ap = A + (size_t)(bm0 + aRow + p * 64) * NDIM          \
                                + (k0) + aK8;                                   \
            ra[2 * p]     = *(const float4*)ap;                                 \
            ra[2 * p + 1] = *(const float4*)(ap + 4);                           \
        }                                                                       \
        _Pragma("unroll")                                                       \
        for (int p = 0; p < 4; ++p)                                             \
            rb[p] = *(const float4*)(B + (size_t)((k0) + bRow + p * 8) * NDIM   \
                                       + bn0 + bCol);                           \
    }

#define STORE_CHUNK(sbuf)                                                       \
    {                                                                           \
        _Pragma("unroll")                                                       \
        for (int p = 0; p < 2; ++p) {                                           \
            uint32_t h01, h23, l01, l23, h45, h67, l45, l67;                    \
            split2(ra[2*p].x, ra[2*p].y, h01, l01);                             \
            split2(ra[2*p].z, ra[2*p].w, h23, l23);                             \
            split2(ra[2*p+1].x, ra[2*p+1].y, h45, l45);                         \
            split2(ra[2*p+1].z, ra[2*p+1].w, h67, l67);                         \
            uint32_t aoff = aoffBase + (uint32_t)(p * 4096);                    \
            sts4((sbuf) + ST_AH + aoff, h01, h23, h45, h67);                    \
            sts4((sbuf) + ST_AL + aoff, l01, l23, l45, l67);                    \
        }                                                                       \
        _Pragma("unroll")                                                       \
        for (int p = 0; p < 4; ++p) {                                           \
            __half2 h0 = __floats2half2_rn(rb[p].x, rb[p].y);                   \
            __half2 h1 = __floats2half2_rn(rb[p].z, rb[p].w);                   \
            int kk = bRow + p * 8;                                              \
            uint32_t boff = (uint32_t)(kk * 256 +                               \
                            ((bCol * 2) ^ ((kk & 7) << 4)));                    \
            sts2((sbuf) + ST_BH + boff, h2u(h0), h2u(h1));                      \
        }                                                                       \
    }

    // prologue
    LOAD_CHUNK(kStart);
    STORE_CHUNK(sbase);
    __syncthreads();

    for (int c = 0; c < nchunks; ++c) {
        const uint32_t scur = sbase + (uint32_t)(c & 1) * STAGE;
        const bool more = (c + 1 < nchunks);
        if (more) LOAD_CHUNK(kStart + (c + 1) * BK);

#pragma unroll
        for (int ks = 0; ks < BK; ks += 16) {
            uint32_t bF[2][4];
#pragma unroll
            for (int ntp = 0; ntp < 2; ++ntp) {
                uint32_t twoN0 = (uint32_t)((n0w + 16 * ntp) * 2);
                uint32_t br = scur + ST_BH + (uint32_t)(ks * 256) + laneBRow +
                              (twoN0 ^ laneBCol);
                ldm4t(bF[ntp], br);
            }
            // A-frags double-buffered across mt (live frag regs = 24)
            uint32_t aH[2][4], aL[2][4];
            {
                const uint32_t ar = scur + (uint32_t)(m0w * 64) +
                                    (laneA ^ (uint32_t)((ks >> 3) << 4));
                ldm4(aH[0], ar);
                ldm4(aL[0], ar + ST_AL);
            }
#pragma unroll
            for (int mt = 0; mt < 4; ++mt) {
                const int cur = mt & 1;
                if (mt < 3) {
                    const uint32_t ar = scur +
                        (uint32_t)((m0w + 16 * (mt + 1)) * 64) +
                        (laneA ^ (uint32_t)((ks >> 3) << 4));
                    ldm4(aH[cur ^ 1], ar);
                    ldm4(aL[cur ^ 1], ar + ST_AL);
                }
#pragma unroll
                for (int nt = 0; nt < 4; ++nt)
                    mma_f16(acc[mt][nt], aH[cur], &bF[nt >> 1][(nt & 1) * 2]);
#pragma unroll
                for (int nt = 0; nt < 4; ++nt)
                    mma_f16(acc[mt][nt], aL[cur], &bF[nt >> 1][(nt & 1) * 2]);
            }
        }

        if (more) STORE_CHUNK(sbase + (uint32_t)((c + 1) & 1) * STAGE);
        __syncthreads();
    }

    // ---- epilogue: tril-masked stores ----
#pragma unroll
    for (int mt = 0; mt < 4; ++mt) {
        const int r0 = bm0 + m0w + 16 * mt + (lane >> 2);
#pragma unroll
        for (int nt = 0; nt < 4; ++nt) {
            const int c0 = bn0 + n0w + 8 * nt + 2 * (lane & 3);
            float* p0 = C + (size_t)r0 * NDIM + c0;
            float* p1 = p0 + 8 * (size_t)NDIM;
            if (c0     <= r0)     p0[0] = acc[mt][nt][0];
            if (c0 + 1 <= r0)     p0[1] = acc[mt][nt][1];
            if (c0     <= r0 + 8) p1[0] = acc[mt][nt][2];
            if (c0 + 1 <= r0 + 8) p1[1] = acc[mt][nt][3];
        }
    }
}

extern "C" void kernel_launch(void* const* d_in, const int* in_sizes, int n_in,
                              void* d_out, int out_size) {
    const float* A = (const float*)d_in[0];
    const float* B = (const float*)d_in[1];
    float* C = (float*)d_out;

    cudaFuncSetAttribute(trimm_f16, cudaFuncAttributeMaxDynamicSharedMemorySize,
                         SMEM_DYN);

    // zero output (kernel never writes the strict upper triangle)
    cudaMemsetAsync(C, 0, (size_t)NDIM * NDIM * sizeof(float), 0);

    const int nblocks = NB * (NB + 1) / 2;   // 528 full lower-triangular tiles
    trimm_f16<<<nblocks, THREADS, SMEM_DYN>>>(A, B, C);
}